// round 1
// baseline (speedup 1.0000x reference)
#include <cuda_runtime.h>
#include <cstdio>

// Shapes (fixed by the problem)
#define B_   8
#define NQ_  75
#define NS_  5
#define NG_  4
#define NF_  49     // nsf == nqf
#define C_   64

// derived
#define ROWS_ 294          // 5*49 support rows + 49 query rows
#define STR_  68           // smem row stride (64 + 4 pad -> odd*4 bank step, conflict free)
#define NT2_  320          // threads kernel2 (294 active, 10 warps)

__device__ float g_p1[B_ * NQ_ * NS_ * NG_];   // mmd_s partials, layout [((b*75+v)*5+s)*4+g]
__device__ float g_p2[B_ * NQ_ * NS_ * NG_];   // (mmd_q - 2*mmd_sq) partials, same layout

// multi-gaussian sum via t-powers: alphas = {1/8,1/4,1/2,1,2}
__device__ __forceinline__ float multi_gauss(float d2) {
    d2 = fmaxf(d2, 0.0f);
    float t  = __expf(-0.125f * d2);
    float t2 = t * t;
    float t4 = t2 * t2;
    float t8 = t4 * t4;
    float t16 = t8 * t8;
    return t + t2 + t4 + t8 + t16;
}

// ---------------------------------------------------------------------------
// Kernel 1: per (b,s,g) block -> Kss (49x49), then beta_v^T Kss beta_v for all v
// ---------------------------------------------------------------------------
__global__ __launch_bounds__(256) void k1_mmd_s(const float* __restrict__ sup,
                                                const float* __restrict__ beta) {
    __shared__ float sraw[49 * 65];
    __shared__ float ssq[49];
    __shared__ float kss[49 * 50];
    __shared__ float betas[NQ_ * 49];   // 75*49
    __shared__ float mmdv[NQ_];

    int bid = blockIdx.x;              // 0..159
    int g = bid & 3;
    int bs = bid >> 2;
    int s = bs % NS_;
    int b = bs / NS_;
    int tid = threadIdx.x;

    const float* sb = sup + (size_t)(((b * NS_ + s) * NG_ + g)) * 49 * 64;
    for (int idx = tid; idx < 49 * 64; idx += 256) {
        int r = idx >> 6, c = idx & 63;
        sraw[r * 65 + c] = sb[idx];
    }
    for (int idx = tid; idx < NQ_ * 49; idx += 256) {
        int v = idx / 49, j = idx - v * 49;
        size_t off = ((size_t)((b * NQ_ + v) * NS_ + s) * NG_ + g) * 49 + j;
        betas[idx] = beta[off];
    }
    if (tid < NQ_) mmdv[tid] = 0.0f;
    __syncthreads();

    for (int r = tid; r < 49; r += 256) {
        float acc = 0.0f;
        const float* xr = sraw + r * 65;
        #pragma unroll
        for (int c = 0; c < 64; c++) acc = fmaf(xr[c], xr[c], acc);
        ssq[r] = acc;
    }
    __syncthreads();

    for (int e = tid; e < 49 * 49; e += 256) {
        int i = e / 49, j = e - i * 49;
        const float* xi = sraw + i * 65;
        const float* xj = sraw + j * 65;
        float d = 0.0f;
        #pragma unroll
        for (int c = 0; c < 64; c++) d = fmaf(xi[c], xj[c], d);
        float d2 = ssq[i] + ssq[j] - 2.0f * d;
        kss[i * 50 + j] = multi_gauss(d2);
    }
    __syncthreads();

    for (int e = tid; e < NQ_ * 49; e += 256) {
        int v = e / 49, i = e - v * 49;
        const float* kr = kss + i * 50;
        const float* bv = betas + v * 49;
        float r = 0.0f;
        #pragma unroll
        for (int j = 0; j < 49; j++) r = fmaf(kr[j], bv[j], r);
        atomicAdd(&mmdv[v], bv[i] * r);
    }
    __syncthreads();

    if (tid < NQ_) {
        int idx = ((b * NQ_ + tid) * NS_ + s) * NG_ + g;
        g_p1[idx] = mmdv[tid];
    }
}

// ---------------------------------------------------------------------------
// Kernel 2: per (b,v,g) block. Rows 0..244 = supports (all 5 s), 245..293 = query.
// Each of 294 threads owns a 7x7 micro-tile of the 294x49 dot matrix.
// Fused: dots -> d2 -> multi_gauss -> bilinear (beta x gamma / gamma x gamma).
// ---------------------------------------------------------------------------
__global__ __launch_bounds__(NT2_, 2) void k2_main(const float* __restrict__ sup,
                                                   const float* __restrict__ qry,
                                                   const float* __restrict__ beta,
                                                   const float* __restrict__ gamma) {
    extern __shared__ float sm[];
    float* xs   = sm;                     // 294*68
    float* rsq  = xs + ROWS_ * STR_;      // 296
    float* bet  = rsq + 296;              // 245
    float* gam  = bet + 245;              // 245
    float* red  = gam + 245;              // 16 (use 10: [0..4]=mmd_sq, [5..9]=mmd_q)

    int bid = blockIdx.x;                 // 0..2399
    int g = bid & 3;
    int bv = bid >> 2;                    // b*75+v
    int v = bv % NQ_;
    int b = bv / NQ_;
    int tid = threadIdx.x;

    const float* supb = sup + (size_t)(b * (NS_ * NG_) + g) * 49 * 64;  // + s*4*3136
    const float* qryb = qry + ((size_t)bv * NG_ + g) * 49 * 64;

    for (int idx = tid; idx < ROWS_ * 64; idx += NT2_) {
        int r = idx >> 6, c = idx & 63;
        float val;
        if (r < 245) {
            int s = r / 49;
            int i = r - s * 49;
            val = supb[(size_t)s * (NG_ * 49 * 64) + i * 64 + c];
        } else {
            val = qryb[(r - 245) * 64 + c];
        }
        xs[r * STR_ + c] = val;
    }
    for (int idx = tid; idx < NS_ * 49; idx += NT2_) {
        int s = idx / 49, j = idx - s * 49;
        size_t off = ((size_t)(bv * NS_ + s) * NG_ + g) * 49 + j;
        bet[idx] = beta[off];
        gam[idx] = gamma[off];
    }
    if (tid < 16) red[tid] = 0.0f;
    __syncthreads();

    for (int r = tid; r < ROWS_; r += NT2_) {
        float acc = 0.0f;
        const float* xr = xs + r * STR_;
        #pragma unroll
        for (int c = 0; c < 64; c++) acc = fmaf(xr[c], xr[c], acc);
        rsq[r] = acc;
    }
    __syncthreads();

    bool active = (tid < ROWS_);
    int it = tid / 7;       // 0..41 (i micro-tile)
    int jt = tid - it * 7;  // 0..6  (j micro-tile)

    float acc[49];
    #pragma unroll
    for (int k = 0; k < 49; k++) acc[k] = 0.0f;

    if (active) {
        const float* A = xs + it * 7 * STR_;
        const float* Bm = xs + (245 + jt * 7) * STR_;
        #pragma unroll 2
        for (int c = 0; c < 64; c++) {
            float a[7], bb[7];
            #pragma unroll
            for (int k = 0; k < 7; k++) a[k] = A[k * STR_ + c];
            #pragma unroll
            for (int k = 0; k < 7; k++) bb[k] = Bm[k * STR_ + c];
            #pragma unroll
            for (int ii = 0; ii < 7; ii++)
                #pragma unroll
                for (int jj = 0; jj < 7; jj++)
                    acc[ii * 7 + jj] = fmaf(a[ii], bb[jj], acc[ii * 7 + jj]);
        }

        // kernel values in place
        float qsq[7];
        int jbase = jt * 7;
        #pragma unroll
        for (int jj = 0; jj < 7; jj++) qsq[jj] = rsq[245 + jbase + jj];
        #pragma unroll
        for (int ii = 0; ii < 7; ii++) {
            float ri = rsq[it * 7 + ii];
            #pragma unroll
            for (int jj = 0; jj < 7; jj++) {
                float d2 = ri + qsq[jj] - 2.0f * acc[ii * 7 + jj];
                acc[ii * 7 + jj] = multi_gauss(d2);
            }
        }

        if (it < 35) {
            // support rows: contributes to mmd_sq for s = it/7
            int s = it / 7;
            int i0 = it * 7 - s * 49;   // 0..42
            const float* gs = gam + s * 49 + jbase;
            const float* bs = bet + s * 49 + i0;
            float partial = 0.0f;
            #pragma unroll
            for (int ii = 0; ii < 7; ii++) {
                float rowsum = 0.0f;
                #pragma unroll
                for (int jj = 0; jj < 7; jj++) rowsum = fmaf(acc[ii * 7 + jj], gs[jj], rowsum);
                partial = fmaf(bs[ii], rowsum, partial);
            }
            atomicAdd(&red[s], partial);
        } else {
            // query rows: Kqq elements, contribute to mmd_q for all 5 s
            int q0 = it * 7 - 245;      // 0..42
            float pq[5];
            #pragma unroll
            for (int s = 0; s < 5; s++) pq[s] = 0.0f;
            #pragma unroll
            for (int ii = 0; ii < 7; ii++) {
                #pragma unroll
                for (int s = 0; s < 5; s++) {
                    const float* gs = gam + s * 49;
                    float rowsum = 0.0f;
                    #pragma unroll
                    for (int jj = 0; jj < 7; jj++) rowsum = fmaf(acc[ii * 7 + jj], gs[jbase + jj], rowsum);
                    pq[s] = fmaf(gs[q0 + ii], rowsum, pq[s]);
                }
            }
            #pragma unroll
            for (int s = 0; s < 5; s++) atomicAdd(&red[5 + s], pq[s]);
        }
    }
    __syncthreads();

    if (tid < NS_) {
        int idx = (bv * NS_ + tid) * NG_ + g;
        g_p2[idx] = red[5 + tid] - 2.0f * red[tid];
    }
}

// ---------------------------------------------------------------------------
// Kernel 3: out[b,v,s] = mean_g (p1 + p2)
// ---------------------------------------------------------------------------
__global__ void k3_reduce(float* __restrict__ out) {
    int o = blockIdx.x * blockDim.x + threadIdx.x;
    if (o < B_ * NQ_ * NS_) {
        float s = 0.0f;
        #pragma unroll
        for (int g = 0; g < NG_; g++) s += g_p1[o * NG_ + g] + g_p2[o * NG_ + g];
        out[o] = 0.25f * s;
    }
}

extern "C" void kernel_launch(void* const* d_in, const int* in_sizes, int n_in,
                              void* d_out, int out_size) {
    const float* sup   = (const float*)d_in[0];  // (8,5,4,49,64)
    const float* qry   = (const float*)d_in[1];  // (8,75,4,49,64)
    const float* beta  = (const float*)d_in[2];  // (8,75,5,4,49)
    const float* gamma = (const float*)d_in[3];  // (8,75,5,4,49)
    float* out = (float*)d_out;                  // (8,75,5)

    const int smem2 = (ROWS_ * STR_ + 296 + 245 + 245 + 16) * (int)sizeof(float);
    static bool configured = false;
    if (!configured) {
        cudaFuncSetAttribute(k2_main, cudaFuncAttributeMaxDynamicSharedMemorySize, smem2);
        configured = true;
    }
    // idempotent safety if first call raced/was before capture
    cudaFuncSetAttribute(k2_main, cudaFuncAttributeMaxDynamicSharedMemorySize, smem2);

    k1_mmd_s<<<B_ * NS_ * NG_, 256>>>(sup, beta);
    k2_main<<<B_ * NQ_ * NG_, NT2_, smem2>>>(sup, qry, beta, gamma);
    k3_reduce<<<(B_ * NQ_ * NS_ + 255) / 256, 256>>>(out);
}

// round 2
// speedup vs baseline: 1.4884x; 1.4884x over previous
#include <cuda_runtime.h>
#include <cstdio>

// Shapes (fixed by the problem)
#define B_   8
#define NQ_  75
#define NS_  5
#define NG_  4
#define NF_  49
#define C_   64

#define ROWS_ 294          // 5*49 support rows + 49 query rows
#define STR_  68           // smem row stride (float4-aligned, conflict-free)
#define NT2_  320          // threads kernel2

__device__ float g_p1[B_ * NQ_ * NS_ * NG_];   // mmd_s partials   [((b*75+v)*5+s)*4+g]
__device__ float g_p2[B_ * NQ_ * NS_ * NG_];   // mmd_q - 2*mmd_sq, same layout

// multi-gaussian via t-powers: alphas = {1/8,1/4,1/2,1,2}
__device__ __forceinline__ float multi_gauss(float d2) {
    d2 = fmaxf(d2, 0.0f);
    float t  = __expf(-0.125f * d2);
    float t2 = t * t;
    float t4 = t2 * t2;
    float t8 = t4 * t4;
    float t16 = t8 * t8;
    return t + t2 + t4 + t8 + t16;
}

// ---------------------------------------------------------------------------
// Kernel 1: grid 800 = (b,s,g) x 5 v-chunks of 15. Each block:
//   Kss (49x49, recomputed per chunk — cheap) -> beta^T Kss beta for 15 v.
// No atomics: scratch array + per-v tree reduce.
// ---------------------------------------------------------------------------
__global__ __launch_bounds__(256) void k1_mmd_s(const float* __restrict__ sup,
                                                const float* __restrict__ beta) {
    __shared__ float sraw[49 * STR_];
    __shared__ float ssq[64];
    __shared__ float kss[49 * 50];
    __shared__ float betas[15 * 50];
    __shared__ float scr[735];

    int bid = blockIdx.x;              // 0..799
    int g = bid & 3;
    int rest = bid >> 2;
    int s = rest % NS_;  rest /= NS_;
    int vt = rest % 5;                 // v chunk
    int b = rest / 5;
    int tid = threadIdx.x;

    const float* sb = sup + (size_t)(((b * NS_ + s) * NG_ + g)) * 49 * 64;
    // vectorized tile load: 49*16 float4
    for (int idx = tid; idx < 49 * 16; idx += 256) {
        int r = idx >> 4, c4 = idx & 15;
        *(float4*)(sraw + r * STR_ + c4 * 4) = *(const float4*)(sb + r * 64 + c4 * 4);
    }
    for (int idx = tid; idx < 15 * 49; idx += 256) {
        int vv = idx / 49, j = idx - vv * 49;
        int v = vt * 15 + vv;
        size_t off = ((size_t)((b * NQ_ + v) * NS_ + s) * NG_ + g) * 49 + j;
        betas[vv * 50 + j] = beta[off];
    }
    __syncthreads();

    if (tid < 49) {
        const float2* xr = (const float2*)(sraw + tid * STR_);
        float a0 = 0.f, a1 = 0.f;
        #pragma unroll
        for (int c = 0; c < 32; c++) { float2 x = xr[c]; a0 = fmaf(x.x, x.x, a0); a1 = fmaf(x.y, x.y, a1); }
        ssq[tid] = a0 + a1;
    }
    __syncthreads();

    for (int e = tid; e < 49 * 49; e += 256) {
        int i = e / 49, j = e - i * 49;
        const float2* xi = (const float2*)(sraw + i * STR_);
        const float2* xj = (const float2*)(sraw + j * STR_);
        float d0 = 0.f, d1 = 0.f;
        #pragma unroll
        for (int c = 0; c < 32; c++) {
            float2 a = xi[c], bb = xj[c];
            d0 = fmaf(a.x, bb.x, d0);
            d1 = fmaf(a.y, bb.y, d1);
        }
        float d2 = ssq[i] + ssq[j] - 2.0f * (d0 + d1);
        kss[i * 50 + j] = multi_gauss(d2);
    }
    __syncthreads();

    // bilinear: 735 tasks (15 v x 49 rows)
    for (int t = tid; t < 735; t += 256) {
        int vv = t / 49, i = t - vv * 49;
        const float2* kr = (const float2*)(kss + i * 50);
        const float2* bv = (const float2*)(betas + vv * 50);
        float r0 = 0.f, r1 = 0.f;
        #pragma unroll
        for (int c = 0; c < 24; c++) {
            float2 kk = kr[c], bb = bv[c];
            r0 = fmaf(kk.x, bb.x, r0);
            r1 = fmaf(kk.y, bb.y, r1);
        }
        float r = r0 + r1 + kss[i * 50 + 48] * betas[vv * 50 + 48];
        scr[t] = betas[vv * 50 + i] * r;
    }
    __syncthreads();

    if (tid < 15) {
        float acc = 0.f;
        #pragma unroll
        for (int k = 0; k < 49; k++) acc += scr[tid * 49 + k];
        int v = vt * 15 + tid;
        g_p1[((b * NQ_ + v) * NS_ + s) * NG_ + g] = acc;
    }
}

// ---------------------------------------------------------------------------
// Kernel 2: per (b,v,g). 294x49 dot matrix via 7x7 micro-tiles, fused
// d2 -> multi_gauss -> bilinear. float2 smem loads, float4 global loads,
// scratch-based reduction (no atomics).
// ---------------------------------------------------------------------------
__global__ __launch_bounds__(NT2_, 2) void k2_main(const float* __restrict__ sup,
                                                   const float* __restrict__ qry,
                                                   const float* __restrict__ beta,
                                                   const float* __restrict__ gamma) {
    extern __shared__ float sm[];
    float* xs   = sm;                     // 294*68
    float* rsq  = xs + ROWS_ * STR_;      // 296
    float* bet  = rsq + 296;              // 245
    float* gam  = bet + 245;              // 245
    float* scr  = gam + 245;              // 245  (mmd_sq partials, s-blocked by tid)
    float* scrq = scr + 245;              // 245  (mmd_q partials, [s*49 + qtid])
    float* red  = scrq + 245;             // 16

    int bid = blockIdx.x;                 // 0..2399
    int g = bid & 3;
    int bv = bid >> 2;                    // b*75+v
    int b = bv / NQ_;
    int tid = threadIdx.x;

    const float* supb = sup + (size_t)(b * (NS_ * NG_) + g) * 49 * 64;
    const float* qryb = qry + ((size_t)bv * NG_ + g) * 49 * 64;

    // float4 tile load: 294*16 vectors
    for (int idx = tid; idx < ROWS_ * 16; idx += NT2_) {
        int r = idx >> 4, c4 = idx & 15;
        float4 val;
        if (r < 245) {
            int s = r / 49;
            int i = r - s * 49;
            val = *(const float4*)(supb + (size_t)s * (NG_ * 49 * 64) + i * 64 + c4 * 4);
        } else {
            val = *(const float4*)(qryb + (r - 245) * 64 + c4 * 4);
        }
        *(float4*)(xs + r * STR_ + c4 * 4) = val;
    }
    for (int idx = tid; idx < NS_ * 49; idx += NT2_) {
        int s = idx / 49, j = idx - s * 49;
        size_t off = ((size_t)(bv * NS_ + s) * NG_ + g) * 49 + j;
        bet[idx] = beta[off];
        gam[idx] = gamma[off];
    }
    __syncthreads();

    for (int r = tid; r < ROWS_; r += NT2_) {
        const float2* xr = (const float2*)(xs + r * STR_);
        float a0 = 0.f, a1 = 0.f;
        #pragma unroll
        for (int c = 0; c < 32; c++) { float2 x = xr[c]; a0 = fmaf(x.x, x.x, a0); a1 = fmaf(x.y, x.y, a1); }
        rsq[r] = a0 + a1;
    }
    __syncthreads();

    bool active = (tid < ROWS_);
    int it = tid / 7;       // 0..41
    int jt = tid - it * 7;  // 0..6

    float acc[49];
    #pragma unroll
    for (int k = 0; k < 49; k++) acc[k] = 0.0f;

    if (active) {
        const float2* A  = (const float2*)(xs + it * 7 * STR_);
        const float2* Bm = (const float2*)(xs + (245 + jt * 7) * STR_);
        #pragma unroll 1
        for (int c2 = 0; c2 < 32; c2++) {
            float2 a[7], bb[7];
            #pragma unroll
            for (int k = 0; k < 7; k++) a[k]  = A[k * (STR_ / 2) + c2];
            #pragma unroll
            for (int k = 0; k < 7; k++) bb[k] = Bm[k * (STR_ / 2) + c2];
            #pragma unroll
            for (int ii = 0; ii < 7; ii++)
                #pragma unroll
                for (int jj = 0; jj < 7; jj++) {
                    acc[ii * 7 + jj] = fmaf(a[ii].x, bb[jj].x, acc[ii * 7 + jj]);
                    acc[ii * 7 + jj] = fmaf(a[ii].y, bb[jj].y, acc[ii * 7 + jj]);
                }
        }

        float qsq[7];
        int jbase = jt * 7;
        #pragma unroll
        for (int jj = 0; jj < 7; jj++) qsq[jj] = rsq[245 + jbase + jj];
        #pragma unroll
        for (int ii = 0; ii < 7; ii++) {
            float ri = rsq[it * 7 + ii];
            #pragma unroll
            for (int jj = 0; jj < 7; jj++) {
                float d2 = ri + qsq[jj] - 2.0f * acc[ii * 7 + jj];
                acc[ii * 7 + jj] = multi_gauss(d2);
            }
        }

        if (it < 35) {
            int s = it / 7;
            int i0 = it * 7 - s * 49;
            const float* gs = gam + s * 49 + jbase;
            const float* bs = bet + s * 49 + i0;
            float partial = 0.0f;
            #pragma unroll
            for (int ii = 0; ii < 7; ii++) {
                float rowsum = 0.0f;
                #pragma unroll
                for (int jj = 0; jj < 7; jj++) rowsum = fmaf(acc[ii * 7 + jj], gs[jj], rowsum);
                partial = fmaf(bs[ii], rowsum, partial);
            }
            scr[tid] = partial;            // tid/49 == s
        } else {
            int q0 = it * 7 - 245;
            int qt = tid - 245;            // 0..48
            #pragma unroll
            for (int s = 0; s < 5; s++) {
                const float* gs = gam + s * 49;
                float pq = 0.0f;
                #pragma unroll
                for (int ii = 0; ii < 7; ii++) {
                    float rowsum = 0.0f;
                    #pragma unroll
                    for (int jj = 0; jj < 7; jj++) rowsum = fmaf(acc[ii * 7 + jj], gs[jbase + jj], rowsum);
                    pq = fmaf(gs[q0 + ii], rowsum, pq);
                }
                scrq[s * 49 + qt] = pq;
            }
        }
    }
    __syncthreads();

    // 10 parallel sums of 49
    if (tid < 10) {
        int s = tid % 5;
        const float* src = (tid < 5) ? (scr + s * 49) : (scrq + s * 49);
        float acc2 = 0.f;
        #pragma unroll
        for (int k = 0; k < 49; k++) acc2 += src[k];
        red[tid] = acc2;
    }
    __syncthreads();

    if (tid < NS_) {
        int idx = (bv * NS_ + tid) * NG_ + g;
        g_p2[idx] = red[5 + tid] - 2.0f * red[tid];
    }
}

// ---------------------------------------------------------------------------
// Kernel 3: out[b,v,s] = mean_g (p1 + p2)
// ---------------------------------------------------------------------------
__global__ void k3_reduce(float* __restrict__ out) {
    int o = blockIdx.x * blockDim.x + threadIdx.x;
    if (o < B_ * NQ_ * NS_) {
        float s = 0.0f;
        #pragma unroll
        for (int g = 0; g < NG_; g++) s += g_p1[o * NG_ + g] + g_p2[o * NG_ + g];
        out[o] = 0.25f * s;
    }
}

extern "C" void kernel_launch(void* const* d_in, const int* in_sizes, int n_in,
                              void* d_out, int out_size) {
    const float* sup   = (const float*)d_in[0];  // (8,5,4,49,64)
    const float* qry   = (const float*)d_in[1];  // (8,75,4,49,64)
    const float* beta  = (const float*)d_in[2];  // (8,75,5,4,49)
    const float* gamma = (const float*)d_in[3];  // (8,75,5,4,49)
    float* out = (float*)d_out;                  // (8,75,5)

    const int smem2 = (ROWS_ * STR_ + 296 + 245 * 4 + 16) * (int)sizeof(float);
    static bool configured = false;
    if (!configured) {
        cudaFuncSetAttribute(k2_main, cudaFuncAttributeMaxDynamicSharedMemorySize, smem2);
        configured = true;
    }

    k1_mmd_s<<<B_ * NS_ * NG_ * 5, 256>>>(sup, beta);
    k2_main<<<B_ * NQ_ * NG_, NT2_, smem2>>>(sup, qry, beta, gamma);
    k3_reduce<<<(B_ * NQ_ * NS_ + 255) / 256, 256>>>(out);
}